// round 12
// baseline (speedup 1.0000x reference)
#include <cuda_runtime.h>
#include <cuda_fp16.h>
#include <cstdint>

#define BATCH 4
#define SEQ   2048
#define EMB   1024
#define HEADS 16
#define HDIM  64
#define MTOT  (BATCH*SEQ)   // 8192

// ---------------- scratch (device globals: allocation-free rule) -------------
__device__ __half g_q[MTOT*EMB];      // fp16, pre-scaled 1/8, [bh][s][d]
__device__ __half g_k[MTOT*EMB];      // fp16, [bh][s][d]
__device__ __half g_v[MTOT*EMB];      // fp16, TRANSPOSED [bh][d][s]
__device__ __half g_ctx[MTOT*EMB];    // fp16, [B,S,E]
__device__ __half g_x[MTOT*EMB];      // fp16 input
__device__ __half g_w[4*EMB*EMB];     // fp16 Wq,Wk,Wv,Wo (contiguous)
__device__ float  g_b[3*EMB];         // packed bq|bk|bv (f32)

// ---------------- PTX helpers ------------------------------------------------
__device__ __forceinline__ uint32_t pack_h2(float lo, float hi){
    __half2 h = __floats2half2_rn(lo, hi);
    return *(uint32_t*)&h;
}
__device__ __forceinline__ void ldsm4(uint32_t a[4], uint32_t saddr){
    asm volatile("ldmatrix.sync.aligned.m8n8.x4.shared.b16 {%0,%1,%2,%3}, [%4];"
        : "=r"(a[0]),"=r"(a[1]),"=r"(a[2]),"=r"(a[3]) : "r"(saddr));
}
__device__ __forceinline__ void mma_f16(float c[4], const uint32_t a[4],
                                        uint32_t b0, uint32_t b1){
    asm volatile(
        "mma.sync.aligned.m16n8k16.row.col.f32.f16.f16.f32 "
        "{%0,%1,%2,%3},{%4,%5,%6,%7},{%8,%9},{%0,%1,%2,%3};"
        : "+f"(c[0]),"+f"(c[1]),"+f"(c[2]),"+f"(c[3])
        : "r"(a[0]),"r"(a[1]),"r"(a[2]),"r"(a[3]),"r"(b0),"r"(b1));
}
__device__ __forceinline__ void cpa16(uint32_t dst, const void* src){
    asm volatile("cp.async.ca.shared.global [%0], [%1], 16;\n" :: "r"(dst), "l"(src));
}
__device__ __forceinline__ void cpa_commit(){ asm volatile("cp.async.commit_group;\n"); }
template<int N> __device__ __forceinline__ void cpa_wait(){
    asm volatile("cp.async.wait_group %0;\n" :: "n"(N));
}

// ---------------- fused prep: f32 -> fp16 x + 4 W, pack biases ---------------
#define N4X (MTOT*EMB/4)     // 2097152
#define N4W (EMB*EMB/4)      // 262144
__device__ __forceinline__ uint2 h4(float4 v){
    uint2 r; r.x = pack_h2(v.x, v.y); r.y = pack_h2(v.z, v.w); return r;
}
__global__ void prep_k(
    const float4* __restrict__ x,
    const float4* __restrict__ Wq, const float4* __restrict__ Wk,
    const float4* __restrict__ Wv, const float4* __restrict__ Wo,
    const float*  __restrict__ bq, const float* __restrict__ bk,
    const float*  __restrict__ bv,
    uint2* __restrict__ xp, uint2* __restrict__ wp, float* __restrict__ bp)
{
    int i = blockIdx.x*blockDim.x + threadIdx.x;
    if(i < N4X){
        xp[i] = h4(x[i]);
    } else if(i < N4X + 4*N4W){
        int j = i - N4X;
        int w = j >> 18;
        int off = j & (N4W-1);
        const float4* src = (w==0)?Wq : (w==1)?Wk : (w==2)?Wv : Wo;
        wp[(size_t)w*N4W + off] = h4(src[off]);
    } else {
        int j = i - (N4X + 4*N4W);
        if(j < 3*EMB){
            int seg = j >> 10, off = j & (EMB-1);
            const float* src = (seg==0)?bq : (seg==1)?bk : bv;
            bp[j] = src[off];
        }
    }
}
#define PREP_TOTAL (N4X + 4*N4W + 3*EMB)

// =============================================================================
// fp16 NT GEMM v2: 128x256 block, 8 warps (2x4), warp tile 64x64, m16n8k16.
// 8 ldsm : 32 mma per k16 step (4:1). 3-stage cp.async, stride-40 fp16 layout.
// fused=1: N=3072 (Wq|Wk|Wv); Q scaled 1/8; V stored transposed [bh][d][s].
// fused=0: flat f32 [M,1024] store.
// =============================================================================
#define GBM 128
#define GBN 256
#define GBK 32
#define ASTRH 40                          // fp16 units
#define A_STG_H (GBM*ASTRH)               // 5120
#define B_STG_H (GBN*ASTRH)               // 10240
#define STG_H   (A_STG_H + B_STG_H)       // 15360
#define GEMM_SMEM_BYTES (3*STG_H*2)       // 92160

__global__ __launch_bounds__(256, 1) void gemm_nt(
    const __half* __restrict__ A, const __half* __restrict__ W,
    const float* __restrict__ bias,
    __half* __restrict__ oQ, __half* __restrict__ oK, __half* __restrict__ oV,
    float* __restrict__ oF, int fused)
{
    extern __shared__ __half smh[];
    const int tid  = threadIdx.x;
    const int lane = tid & 31;
    const int wid  = tid >> 5;
    const int wm   = wid & 1, wn = wid >> 1;   // 2 (M) x 4 (N)
    const int m0 = blockIdx.y * GBM;
    const int n0 = blockIdx.x * GBN;
    const uint32_t sbase = (uint32_t)__cvta_generic_to_shared(smh);

    auto load_stage = [&](int kt, int st){
        const int k0 = kt*GBK;
        const int baseh = st*STG_H;
        const __half* ag = A + (size_t)m0*EMB + k0;
        #pragma unroll
        for(int i=0;i<2;i++){
            int idx = tid + i*256;
            int r = idx>>2, c16 = idx&3;
            cpa16(sbase + (uint32_t)(2*(baseh + r*ASTRH + c16*8)),
                  ag + (size_t)r*EMB + c16*8);
        }
        const __half* wg = W + (size_t)n0*EMB + k0;
        #pragma unroll
        for(int i=0;i<4;i++){
            int idx = tid + i*256;
            int r = idx>>2, c16 = idx&3;
            cpa16(sbase + (uint32_t)(2*(baseh + A_STG_H + r*ASTRH + c16*8)),
                  wg + (size_t)r*EMB + c16*8);
        }
        cpa_commit();
    };

    // ldmatrix lane offsets (fp16 units)
    const int q8 = lane >> 3, lr = lane & 7;
    uint32_t aoff[4], boff[4];
    #pragma unroll
    for(int im=0; im<4; im++)
        aoff[im] = (uint32_t)((wm*64 + im*16 + (lane&15))*ASTRH + (lane>>4)*8);
    #pragma unroll
    for(int p=0; p<4; p++)
        boff[p] = (uint32_t)(A_STG_H +
                   (wn*64 + p*16 + (q8>>1)*8 + lr)*ASTRH + (q8&1)*8);

    float acc[4][8][4] = {};

    load_stage(0, 0);
    load_stage(1, 1);
    const int NKT = EMB/GBK;   // 32
    for(int kt=0; kt<NKT; kt++){
        if(kt == NKT-1) cpa_wait<0>(); else cpa_wait<1>();
        __syncthreads();
        const uint32_t baseh = (uint32_t)((kt % 3)*STG_H);

        #pragma unroll
        for(int ks=0; ks<2; ks++){            // two k16 steps per K=32 chunk
            uint32_t a[4][4];
            #pragma unroll
            for(int im=0; im<4; im++)
                ldsm4(a[im], sbase + 2*(baseh + aoff[im] + ks*16));
            #pragma unroll
            for(int p=0; p<4; p++){
                uint32_t bf[4];
                ldsm4(bf, sbase + 2*(baseh + boff[p] + ks*16));
                #pragma unroll
                for(int im=0; im<4; im++){
                    mma_f16(acc[im][2*p  ], a[im], bf[0], bf[1]);
                    mma_f16(acc[im][2*p+1], a[im], bf[2], bf[3]);
                }
            }
        }
        if(kt+2 < NKT) load_stage(kt+2, (kt+2)%3);
    }

    // ---- epilogue ----
    int seg = 0;
    float scale = 1.0f;
    __half* outp = oQ;
    int n0s = n0;
    if(fused){
        seg  = n0 >> 10;
        n0s  = n0 & 1023;
        outp = (seg==0) ? oQ : (seg==1) ? oK : oV;
        scale = (seg==0) ? 0.125f : 1.0f;
    }
    #pragma unroll
    for(int im=0; im<4; im++){
        #pragma unroll
        for(int jn=0; jn<8; jn++){
            int nc = wn*64 + jn*8 + (lane&3)*2;
            float b0 = bias[n0+nc], b1 = bias[n0+nc+1];
            #pragma unroll
            for(int half_=0; half_<2; half_++){
                int r = m0 + wm*64 + im*16 + (lane>>2) + half_*8;
                float v0 = acc[im][jn][half_*2+0] + b0;
                float v1 = acc[im][jn][half_*2+1] + b1;
                if(fused){
                    int bidx = r >> 11;
                    int srow = r & (SEQ-1);
                    int ncol = n0s + nc;
                    int head = ncol >> 6, d = ncol & 63;
                    size_t bh = (size_t)(bidx*HEADS + head);
                    if(seg == 2){
                        outp[(bh*HDIM + d  )*SEQ + srow] = __float2half_rn(v0);
                        outp[(bh*HDIM + d+1)*SEQ + srow] = __float2half_rn(v1);
                    }else{
                        *(uint32_t*)&outp[(bh*SEQ + srow)*HDIM + d] =
                            pack_h2(v0*scale, v1*scale);
                    }
                }else{
                    *(float2*)&oF[(size_t)r*EMB + n0 + nc] = make_float2(v0, v1);
                }
            }
        }
    }
}

// =============================================================================
// Flash attention fp16 (unchanged from R11): 128 threads, FBQ=128, M_warp=32,
// m16n8k16, fp32 accum + softmax, stride-72 fp16 smem.
// =============================================================================
#define FBQ 128
#define FBK 64
#define KSTRH 72
#define KS_H   0
#define KSTG_H (FBK*KSTRH)                // 4608
#define VS_H   (2*KSTG_H)                 // 9216
#define VSTG_H (HDIM*KSTRH)               // 4608
#define QP_H   (VS_H + 2*VSTG_H)          // 18432
#define QP_SZ_H (FBQ*KSTRH)               // 9216
#define BI_H   (QP_H + QP_SZ_H)           // 27648 halves
#define FLASH_SMEM_BYTES (BI_H*2 + 2*FBK*4 + 64)

__global__ __launch_bounds__(128, 2) void flash_attn(
    const __half* __restrict__ Qg_, const __half* __restrict__ Kg_,
    const __half* __restrict__ Vg_, const int* __restrict__ mask,
    __half* __restrict__ ctx)
{
    extern __shared__ __half smh[];
    float* smf = (float*)(smh + BI_H);
    const uint32_t sbase = (uint32_t)__cvta_generic_to_shared(smh);
    const int tid = threadIdx.x, lane = tid&31, w = tid>>5;
    const int bh = blockIdx.y, b = bh>>4, h = bh&15;
    const int q0 = blockIdx.x * FBQ;
    const __half* Qg = Qg_ + (size_t)bh*SEQ*HDIM;
    const __half* Kg = Kg_ + (size_t)bh*SEQ*HDIM;
    const __half* Vg = Vg_ + (size_t)bh*HDIM*SEQ;   // [d][s]

    #pragma unroll
    for(int i=0;i<8;i++){
        int idx = tid + i*128;
        int r = idx>>3, c16 = idx&7;
        cpa16(sbase + (uint32_t)(2*(QP_H + r*KSTRH + c16*8)),
              Qg + (size_t)(q0+r)*HDIM + c16*8);
    }
    cpa_commit();

    auto loadKV = [&](int kt, int st){
        const int k0 = kt*FBK;
        #pragma unroll
        for(int i=0;i<4;i++){
            int idx = tid + i*128;
            int r = idx>>3, c16 = idx&7;
            cpa16(sbase + (uint32_t)(2*(KS_H + st*KSTG_H + r*KSTRH + c16*8)),
                  Kg + (size_t)(k0+r)*HDIM + c16*8);
        }
        #pragma unroll
        for(int i=0;i<4;i++){
            int idx = tid + i*128;
            int r = idx>>3, c16 = idx&7;   // r = d row
            cpa16(sbase + (uint32_t)(2*(VS_H + st*VSTG_H + r*KSTRH + c16*8)),
                  Vg + (size_t)r*SEQ + k0 + c16*8);
        }
        if(tid < FBK){
            int mv = mask[b*SEQ + k0 + tid];
            smf[st*FBK + tid] = mv ? 0.0f : -1e9f;
        }
        cpa_commit();
    };
    loadKV(0, 0);

    cpa_wait<1>();   // Q ready
    __syncthreads();

    const int q8 = lane >> 3, lr = lane & 7;
    uint32_t koff[4], poff[2];
    #pragma unroll
    for(int p=0; p<4; p++)
        koff[p] = (uint32_t)((p*16 + (q8>>1)*8 + lr)*KSTRH + (q8&1)*8);
    #pragma unroll
    for(int im=0; im<2; im++)
        poff[im] = (uint32_t)(QP_H + (w*32 + im*16 + (lane&15))*KSTRH + (lane>>4)*8);

    uint32_t qf[4][2][4];
    #pragma unroll
    for(int kd=0; kd<4; kd++)
        #pragma unroll
        for(int im=0; im<2; im++)
            ldsm4(qf[kd][im], sbase + 2*(poff[im] + kd*16));

    float m_[2][2] = {{-1e30f,-1e30f},{-1e30f,-1e30f}};
    float l_[2][2] = {{0.f,0.f},{0.f,0.f}};
    float o[2][8][4] = {};

    const int NT = SEQ/FBK;   // 32
    for(int kt=0; kt<NT; kt++){
        if(kt+1 < NT){ loadKV(kt+1, (kt+1)&1); cpa_wait<1>(); }
        else         { cpa_wait<0>(); }
        __syncthreads();
        const int st = kt & 1;
        const uint32_t kb = (uint32_t)(KS_H + st*KSTG_H);
        const uint32_t vb = (uint32_t)(VS_H + st*VSTG_H);

        float s[2][8][4] = {};
        #pragma unroll
        for(int kd=0; kd<4; kd++){
            #pragma unroll
            for(int p=0; p<4; p++){
                uint32_t kf[4];
                ldsm4(kf, sbase + 2*(kb + koff[p] + kd*16));
                mma_f16(s[0][2*p  ], qf[kd][0], kf[0], kf[1]);
                mma_f16(s[1][2*p  ], qf[kd][1], kf[0], kf[1]);
                mma_f16(s[0][2*p+1], qf[kd][0], kf[2], kf[3]);
                mma_f16(s[1][2*p+1], qf[kd][1], kf[2], kf[3]);
            }
        }

        #pragma unroll
        for(int im=0; im<2; im++){
            float tm0 = -1e30f, tm1 = -1e30f;
            #pragma unroll
            for(int jn=0; jn<8; jn++){
                int col = jn*8 + (lane&3)*2;
                float bb0 = smf[st*FBK + col];
                float bb1 = smf[st*FBK + col+1];
                s[im][jn][0] += bb0; tm0 = fmaxf(tm0, s[im][jn][0]);
                s[im][jn][1] += bb1; tm0 = fmaxf(tm0, s[im][jn][1]);
                s[im][jn][2] += bb0; tm1 = fmaxf(tm1, s[im][jn][2]);
                s[im][jn][3] += bb1; tm1 = fmaxf(tm1, s[im][jn][3]);
            }
            tm0 = fmaxf(tm0, __shfl_xor_sync(0xffffffffu, tm0, 1));
            tm0 = fmaxf(tm0, __shfl_xor_sync(0xffffffffu, tm0, 2));
            tm1 = fmaxf(tm1, __shfl_xor_sync(0xffffffffu, tm1, 1));
            tm1 = fmaxf(tm1, __shfl_xor_sync(0xffffffffu, tm1, 2));
            float mn0 = fmaxf(m_[im][0], tm0), mn1 = fmaxf(m_[im][1], tm1);
            float al0 = __expf(m_[im][0]-mn0), al1 = __expf(m_[im][1]-mn1);
            m_[im][0] = mn0; m_[im][1] = mn1;
            float rs0 = 0.f, rs1 = 0.f;
            #pragma unroll
            for(int jn=0; jn<8; jn++){
                s[im][jn][0] = __expf(s[im][jn][0]-mn0); rs0 += s[im][jn][0];
                s[im][jn][1] = __expf(s[im][jn][1]-mn0); rs0 += s[im][jn][1];
                s[im][jn][2] = __expf(s[im][jn][2]-mn1); rs1 += s[im][jn][2];
                s[im][jn][3] = __expf(s[im][jn][3]-mn1); rs1 += s[im][jn][3];
            }
            rs0 += __shfl_xor_sync(0xffffffffu, rs0, 1);
            rs0 += __shfl_xor_sync(0xffffffffu, rs0, 2);
            rs1 += __shfl_xor_sync(0xffffffffu, rs1, 1);
            rs1 += __shfl_xor_sync(0xffffffffu, rs1, 2);
            l_[im][0] = l_[im][0]*al0 + rs0;
            l_[im][1] = l_[im][1]*al1 + rs1;
            #pragma unroll
            for(int jd=0; jd<8; jd++){
                o[im][jd][0]*=al0; o[im][jd][1]*=al0;
                o[im][jd][2]*=al1; o[im][jd][3]*=al1;
            }
        }

        #pragma unroll
        for(int im=0; im<2; im++){
            int pr = w*32 + im*16 + (lane>>2);
            #pragma unroll
            for(int jn=0; jn<8; jn++){
                int cc = jn*8 + (lane&3)*2;
                *(uint32_t*)&smh[QP_H + pr*KSTRH + cc] =
                    pack_h2(s[im][jn][0], s[im][jn][1]);
                *(uint32_t*)&smh[QP_H + (pr+8)*KSTRH + cc] =
                    pack_h2(s[im][jn][2], s[im][jn][3]);
            }
        }
        __syncwarp();

        #pragma unroll
        for(int kk=0; kk<4; kk++){
            uint32_t pf[2][4];
            ldsm4(pf[0], sbase + 2*(poff[0] + kk*16));
            ldsm4(pf[1], sbase + 2*(poff[1] + kk*16));
            #pragma unroll
            for(int p=0; p<4; p++){
                uint32_t vf[4];
                ldsm4(vf, sbase + 2*(vb + koff[p] + kk*16));
                mma_f16(o[0][2*p  ], pf[0], vf[0], vf[1]);
                mma_f16(o[1][2*p  ], pf[1], vf[0], vf[1]);
                mma_f16(o[0][2*p+1], pf[0], vf[2], vf[3]);
                mma_f16(o[1][2*p+1], pf[1], vf[2], vf[3]);
            }
        }
        __syncthreads();
    }

    #pragma unroll
    for(int im=0; im<2; im++){
        float inv0 = 1.0f/l_[im][0], inv1 = 1.0f/l_[im][1];
        int gr0 = q0 + w*32 + im*16 + (lane>>2);
        #pragma unroll
        for(int jd=0; jd<8; jd++){
            int col = h*HDIM + jd*8 + (lane&3)*2;
            *(uint32_t*)&ctx[(size_t)(b*SEQ + gr0  )*EMB + col] =
                pack_h2(o[im][jd][0]*inv0, o[im][jd][1]*inv0);
            *(uint32_t*)&ctx[(size_t)(b*SEQ + gr0+8)*EMB + col] =
                pack_h2(o[im][jd][2]*inv1, o[im][jd][3]*inv1);
        }
    }
}

// =============================================================================
extern "C" void kernel_launch(void* const* d_in, const int* in_sizes, int n_in,
                              void* d_out, int out_size)
{
    const float* x    = (const float*)d_in[0];
    const int*   mask = (const int*)  d_in[1];
    const float* Wq   = (const float*)d_in[2];
    const float* bq   = (const float*)d_in[3];
    const float* Wk   = (const float*)d_in[4];
    const float* bk   = (const float*)d_in[5];
    const float* Wv   = (const float*)d_in[6];
    const float* bv   = (const float*)d_in[7];
    const float* Wo   = (const float*)d_in[8];
    const float* bo   = (const float*)d_in[9];
    float* out = (float*)d_out;

    __half *qp, *kp, *vp, *cp, *xp, *wp;
    float *bp;
    cudaGetSymbolAddress((void**)&qp, g_q);
    cudaGetSymbolAddress((void**)&kp, g_k);
    cudaGetSymbolAddress((void**)&vp, g_v);
    cudaGetSymbolAddress((void**)&cp, g_ctx);
    cudaGetSymbolAddress((void**)&xp, g_x);
    cudaGetSymbolAddress((void**)&wp, g_w);
    cudaGetSymbolAddress((void**)&bp, g_b);

    cudaFuncSetAttribute(gemm_nt,   cudaFuncAttributeMaxDynamicSharedMemorySize, GEMM_SMEM_BYTES);
    cudaFuncSetAttribute(flash_attn,cudaFuncAttributeMaxDynamicSharedMemorySize, FLASH_SMEM_BYTES);

    // 1) fused prep (f32 -> fp16)
    prep_k<<<(PREP_TOTAL+255)/256, 256>>>(
        (const float4*)x, (const float4*)Wq, (const float4*)Wk,
        (const float4*)Wv, (const float4*)Wo,
        bq, bk, bv,
        (uint2*)xp, (uint2*)wp, bp);

    // 2) fused QKV projection (N=3072)
    dim3 gqkv(3*EMB/GBN, MTOT/GBM);  // (12, 64)
    gemm_nt<<<gqkv, 256, GEMM_SMEM_BYTES>>>(xp, wp, bp, qp, kp, vp, nullptr, 1);

    // 3) flash attention
    dim3 fg(SEQ/FBQ, BATCH*HEADS);   // (16, 64)
    flash_attn<<<fg, 128, FLASH_SMEM_BYTES>>>(qp, kp, vp, mask, cp);

    // 4) output projection (f32 out)
    dim3 go(EMB/GBN, MTOT/GBM);      // (4, 64)
    gemm_nt<<<go, 256, GEMM_SMEM_BYTES>>>(cp, wp+3*(size_t)EMB*EMB, bo,
                                          nullptr, nullptr, nullptr, out, 0);
}

// round 13
// speedup vs baseline: 1.1150x; 1.1150x over previous
#include <cuda_runtime.h>
#include <cuda_fp16.h>
#include <cstdint>

#define BATCH 4
#define SEQ   2048
#define EMB   1024
#define HEADS 16
#define HDIM  64
#define MTOT  (BATCH*SEQ)   // 8192

// ---------------- scratch (device globals: allocation-free rule) -------------
__device__ __half g_q[MTOT*EMB];      // fp16, pre-scaled 1/8*log2e, [bh][s][d]
__device__ __half g_k[MTOT*EMB];      // fp16, [bh][s][d]
__device__ __half g_v[MTOT*EMB];      // fp16, TRANSPOSED [bh][d][s]
__device__ __half g_ctx[MTOT*EMB];    // fp16, [B,S,E]
__device__ __half g_x[MTOT*EMB];      // fp16 input
__device__ __half g_w[4*EMB*EMB];     // fp16 Wq,Wk,Wv,Wo (contiguous)
__device__ float  g_b[3*EMB];         // packed bq|bk|bv (f32)

// ---------------- PTX helpers ------------------------------------------------
__device__ __forceinline__ uint32_t pack_h2(float lo, float hi){
    __half2 h = __floats2half2_rn(lo, hi);
    return *(uint32_t*)&h;
}
__device__ __forceinline__ void ldsm4(uint32_t a[4], uint32_t saddr){
    asm volatile("ldmatrix.sync.aligned.m8n8.x4.shared.b16 {%0,%1,%2,%3}, [%4];"
        : "=r"(a[0]),"=r"(a[1]),"=r"(a[2]),"=r"(a[3]) : "r"(saddr));
}
__device__ __forceinline__ void mma_f16(float c[4], const uint32_t a[4],
                                        uint32_t b0, uint32_t b1){
    asm volatile(
        "mma.sync.aligned.m16n8k16.row.col.f32.f16.f16.f32 "
        "{%0,%1,%2,%3},{%4,%5,%6,%7},{%8,%9},{%0,%1,%2,%3};"
        : "+f"(c[0]),"+f"(c[1]),"+f"(c[2]),"+f"(c[3])
        : "r"(a[0]),"r"(a[1]),"r"(a[2]),"r"(a[3]),"r"(b0),"r"(b1));
}
__device__ __forceinline__ void cpa16(uint32_t dst, const void* src){
    asm volatile("cp.async.ca.shared.global [%0], [%1], 16;\n" :: "r"(dst), "l"(src));
}
__device__ __forceinline__ void cpa_commit(){ asm volatile("cp.async.commit_group;\n"); }
template<int N> __device__ __forceinline__ void cpa_wait(){
    asm volatile("cp.async.wait_group %0;\n" :: "n"(N));
}

// ---------------- fused prep: f32 -> fp16 x + 4 W, pack biases ---------------
#define N4X (MTOT*EMB/4)     // 2097152
#define N4W (EMB*EMB/4)      // 262144
__device__ __forceinline__ uint2 h4(float4 v){
    uint2 r; r.x = pack_h2(v.x, v.y); r.y = pack_h2(v.z, v.w); return r;
}
__global__ void prep_k(
    const float4* __restrict__ x,
    const float4* __restrict__ Wq, const float4* __restrict__ Wk,
    const float4* __restrict__ Wv, const float4* __restrict__ Wo,
    const float*  __restrict__ bq, const float* __restrict__ bk,
    const float*  __restrict__ bv,
    uint2* __restrict__ xp, uint2* __restrict__ wp, float* __restrict__ bp)
{
    int i = blockIdx.x*blockDim.x + threadIdx.x;
    if(i < N4X){
        xp[i] = h4(x[i]);
    } else if(i < N4X + 4*N4W){
        int j = i - N4X;
        int w = j >> 18;
        int off = j & (N4W-1);
        const float4* src = (w==0)?Wq : (w==1)?Wk : (w==2)?Wv : Wo;
        wp[(size_t)w*N4W + off] = h4(src[off]);
    } else {
        int j = i - (N4X + 4*N4W);
        if(j < 3*EMB){
            int seg = j >> 10, off = j & (EMB-1);
            const float* src = (seg==0)?bq : (seg==1)?bk : bv;
            bp[j] = src[off];
        }
    }
}
#define PREP_TOTAL (N4X + 4*N4W + 3*EMB)

// Q pre-scale: (1/8) * log2(e), so softmax can run in exp2 domain.
#define QSCALE (0.125f * 1.44269504f)

// =============================================================================
// fp16 NT GEMM (R11 config): 128x128 block, 8 warps (2x4), warp tile 64x32,
// m16n8k16, 3-stage cp.async, stride-40 fp16, 2 CTAs/SM.
// fused=1: N=3072 (Wq|Wk|Wv); Q scaled QSCALE; V stored transposed [bh][d][s].
// fused=0: flat f32 [M,1024] store.
// =============================================================================
#define GBM 128
#define GBN 128
#define GBK 32
#define ASTRH 40                          // fp16 units
#define A_STG_H (GBM*ASTRH)               // 5120
#define B_STG_H (GBN*ASTRH)               // 5120
#define STG_H   (A_STG_H + B_STG_H)       // 10240
#define GEMM_SMEM_BYTES (3*STG_H*2)       // 61440

__global__ __launch_bounds__(256, 2) void gemm_nt(
    const __half* __restrict__ A, const __half* __restrict__ W,
    const float* __restrict__ bias,
    __half* __restrict__ oQ, __half* __restrict__ oK, __half* __restrict__ oV,
    float* __restrict__ oF, int fused)
{
    extern __shared__ __half smh[];
    const int tid  = threadIdx.x;
    const int lane = tid & 31;
    const int wid  = tid >> 5;
    const int wm   = wid & 1, wn = wid >> 1;   // 2 (M) x 4 (N)
    const int m0 = blockIdx.y * GBM;
    const int n0 = blockIdx.x * GBN;
    const uint32_t sbase = (uint32_t)__cvta_generic_to_shared(smh);

    auto load_stage = [&](int kt, int st){
        const int k0 = kt*GBK;
        const int baseh = st*STG_H;
        const __half* ag = A + (size_t)m0*EMB + k0;
        #pragma unroll
        for(int i=0;i<2;i++){
            int idx = tid + i*256;
            int r = idx>>2, c16 = idx&3;
            cpa16(sbase + (uint32_t)(2*(baseh + r*ASTRH + c16*8)),
                  ag + (size_t)r*EMB + c16*8);
        }
        const __half* wg = W + (size_t)n0*EMB + k0;
        #pragma unroll
        for(int i=0;i<2;i++){
            int idx = tid + i*256;
            int r = idx>>2, c16 = idx&3;
            cpa16(sbase + (uint32_t)(2*(baseh + A_STG_H + r*ASTRH + c16*8)),
                  wg + (size_t)r*EMB + c16*8);
        }
        cpa_commit();
    };

    // ldmatrix lane offsets (fp16 units)
    const int q8 = lane >> 3, lr = lane & 7;
    uint32_t aoff[4], boff[2];
    #pragma unroll
    for(int im=0; im<4; im++)
        aoff[im] = (uint32_t)((wm*64 + im*16 + (lane&15))*ASTRH + (lane>>4)*8);
    #pragma unroll
    for(int p=0; p<2; p++)
        boff[p] = (uint32_t)(A_STG_H +
                   (wn*32 + p*16 + (q8>>1)*8 + lr)*ASTRH + (q8&1)*8);

    float acc[4][4][4] = {};

    load_stage(0, 0);
    load_stage(1, 1);
    const int NKT = EMB/GBK;   // 32
    for(int kt=0; kt<NKT; kt++){
        if(kt == NKT-1) cpa_wait<0>(); else cpa_wait<1>();
        __syncthreads();
        const uint32_t baseh = (uint32_t)((kt % 3)*STG_H);

        #pragma unroll
        for(int ks=0; ks<2; ks++){            // two k16 steps per K=32 chunk
            uint32_t a[4][4];
            #pragma unroll
            for(int im=0; im<4; im++)
                ldsm4(a[im], sbase + 2*(baseh + aoff[im] + ks*16));
            #pragma unroll
            for(int p=0; p<2; p++){
                uint32_t bf[4];
                ldsm4(bf, sbase + 2*(baseh + boff[p] + ks*16));
                #pragma unroll
                for(int im=0; im<4; im++){
                    mma_f16(acc[im][2*p  ], a[im], bf[0], bf[1]);
                    mma_f16(acc[im][2*p+1], a[im], bf[2], bf[3]);
                }
            }
        }
        if(kt+2 < NKT) load_stage(kt+2, (kt+2)%3);
    }

    // ---- epilogue ----
    int seg = 0;
    float scale = 1.0f;
    __half* outp = oQ;
    int n0s = n0;
    if(fused){
        seg  = n0 >> 10;
        n0s  = n0 & 1023;
        outp = (seg==0) ? oQ : (seg==1) ? oK : oV;
        scale = (seg==0) ? QSCALE : 1.0f;
    }
    #pragma unroll
    for(int im=0; im<4; im++){
        #pragma unroll
        for(int jn=0; jn<4; jn++){
            int nc = wn*32 + jn*8 + (lane&3)*2;
            float b0 = bias[n0+nc], b1 = bias[n0+nc+1];
            #pragma unroll
            for(int half_=0; half_<2; half_++){
                int r = m0 + wm*64 + im*16 + (lane>>2) + half_*8;
                float v0 = acc[im][jn][half_*2+0] + b0;
                float v1 = acc[im][jn][half_*2+1] + b1;
                if(fused){
                    int bidx = r >> 11;
                    int srow = r & (SEQ-1);
                    int ncol = n0s + nc;
                    int head = ncol >> 6, d = ncol & 63;
                    size_t bh = (size_t)(bidx*HEADS + head);
                    if(seg == 2){
                        outp[(bh*HDIM + d  )*SEQ + srow] = __float2half_rn(v0);
                        outp[(bh*HDIM + d+1)*SEQ + srow] = __float2half_rn(v1);
                    }else{
                        *(uint32_t*)&outp[(bh*SEQ + srow)*HDIM + d] =
                            pack_h2(v0*scale, v1*scale);
                    }
                }else{
                    *(float2*)&oF[(size_t)r*EMB + n0 + nc] = make_float2(v0, v1);
                }
            }
        }
    }
}

// =============================================================================
// Flash attention fp16 v3: 128 threads (4 warps), FBQ=128, M_warp=32.
// P fed to PV mma DIRECTLY from registers (C-frag == A-frag layout trick):
// no P smem region, no P store/ldsm, no syncwarp. exp2-domain softmax.
// =============================================================================
#define FBQ 128
#define FBK 64
#define KSTRH 72
#define KS_H   0
#define KSTG_H (FBK*KSTRH)                // 4608
#define VS_H   (2*KSTG_H)                 // 9216
#define VSTG_H (HDIM*KSTRH)               // 4608
#define Q_H    (VS_H + 2*VSTG_H)          // 18432
#define Q_SZ_H (FBQ*KSTRH)                // 9216
#define BI_H   (Q_H + Q_SZ_H)             // 27648 halves
#define FLASH_SMEM_BYTES (BI_H*2 + 2*FBK*4 + 64)

__global__ __launch_bounds__(128, 2) void flash_attn(
    const __half* __restrict__ Qg_, const __half* __restrict__ Kg_,
    const __half* __restrict__ Vg_, const int* __restrict__ mask,
    __half* __restrict__ ctx)
{
    extern __shared__ __half smh[];
    float* smf = (float*)(smh + BI_H);
    const uint32_t sbase = (uint32_t)__cvta_generic_to_shared(smh);
    const int tid = threadIdx.x, lane = tid&31, w = tid>>5;
    const int bh = blockIdx.y, b = bh>>4, h = bh&15;
    const int q0 = blockIdx.x * FBQ;
    const __half* Qg = Qg_ + (size_t)bh*SEQ*HDIM;
    const __half* Kg = Kg_ + (size_t)bh*SEQ*HDIM;
    const __half* Vg = Vg_ + (size_t)bh*HDIM*SEQ;   // [d][s]

    #pragma unroll
    for(int i=0;i<8;i++){
        int idx = tid + i*128;
        int r = idx>>3, c16 = idx&7;
        cpa16(sbase + (uint32_t)(2*(Q_H + r*KSTRH + c16*8)),
              Qg + (size_t)(q0+r)*HDIM + c16*8);
    }
    cpa_commit();

    auto loadKV = [&](int kt, int st){
        const int k0 = kt*FBK;
        #pragma unroll
        for(int i=0;i<4;i++){
            int idx = tid + i*128;
            int r = idx>>3, c16 = idx&7;
            cpa16(sbase + (uint32_t)(2*(KS_H + st*KSTG_H + r*KSTRH + c16*8)),
                  Kg + (size_t)(k0+r)*HDIM + c16*8);
        }
        #pragma unroll
        for(int i=0;i<4;i++){
            int idx = tid + i*128;
            int r = idx>>3, c16 = idx&7;   // r = d row
            cpa16(sbase + (uint32_t)(2*(VS_H + st*VSTG_H + r*KSTRH + c16*8)),
                  Vg + (size_t)r*SEQ + k0 + c16*8);
        }
        if(tid < FBK){
            int mv = mask[b*SEQ + k0 + tid];
            smf[st*FBK + tid] = mv ? 0.0f : -1e9f;
        }
        cpa_commit();
    };
    loadKV(0, 0);

    cpa_wait<1>();   // Q ready
    __syncthreads();

    const int q8 = lane >> 3, lr = lane & 7;
    uint32_t koff[4], qoff[2];
    #pragma unroll
    for(int p=0; p<4; p++)
        koff[p] = (uint32_t)((p*16 + (q8>>1)*8 + lr)*KSTRH + (q8&1)*8);
    #pragma unroll
    for(int im=0; im<2; im++)
        qoff[im] = (uint32_t)(Q_H + (w*32 + im*16 + (lane&15))*KSTRH + (lane>>4)*8);

    // Q fragments -> registers (4 k16-steps over d=64)
    uint32_t qf[4][2][4];
    #pragma unroll
    for(int kd=0; kd<4; kd++)
        #pragma unroll
        for(int im=0; im<2; im++)
            ldsm4(qf[kd][im], sbase + 2*(qoff[im] + kd*16));

    float m_[2][2] = {{-1e30f,-1e30f},{-1e30f,-1e30f}};
    float l_[2][2] = {{0.f,0.f},{0.f,0.f}};
    float o[2][8][4] = {};

    const int NT = SEQ/FBK;   // 32
    for(int kt=0; kt<NT; kt++){
        if(kt+1 < NT){ loadKV(kt+1, (kt+1)&1); cpa_wait<1>(); }
        else         { cpa_wait<0>(); }
        __syncthreads();
        const int st = kt & 1;
        const uint32_t kb = (uint32_t)(KS_H + st*KSTG_H);
        const uint32_t vb = (uint32_t)(VS_H + st*VSTG_H);

        // ---- S = Q K^T (Q pre-scaled 1/8*log2e) ----
        float s[2][8][4] = {};
        #pragma unroll
        for(int kd=0; kd<4; kd++){
            #pragma unroll
            for(int p=0; p<4; p++){
                uint32_t kf[4];
                ldsm4(kf, sbase + 2*(kb + koff[p] + kd*16));
                mma_f16(s[0][2*p  ], qf[kd][0], kf[0], kf[1]);
                mma_f16(s[1][2*p  ], qf[kd][1], kf[0], kf[1]);
                mma_f16(s[0][2*p+1], qf[kd][0], kf[2], kf[3]);
                mma_f16(s[1][2*p+1], qf[kd][1], kf[2], kf[3]);
            }
        }

        // ---- online softmax in exp2 domain ----
        #pragma unroll
        for(int im=0; im<2; im++){
            float tm0 = -1e30f, tm1 = -1e30f;
            #pragma unroll
            for(int jn=0; jn<8; jn++){
                int col = jn*8 + (lane&3)*2;
                float bb0 = smf[st*FBK + col];
                float bb1 = smf[st*FBK + col+1];
                s[im][jn][0] += bb0; tm0 = fmaxf(tm0, s[im][jn][0]);
                s[im][jn][1] += bb1; tm0 = fmaxf(tm0, s[im][jn][1]);
                s[im][jn][2] += bb0; tm1 = fmaxf(tm1, s[im][jn][2]);
                s[im][jn][3] += bb1; tm1 = fmaxf(tm1, s[im][jn][3]);
            }
            tm0 = fmaxf(tm0, __shfl_xor_sync(0xffffffffu, tm0, 1));
            tm0 = fmaxf(tm0, __shfl_xor_sync(0xffffffffu, tm0, 2));
            tm1 = fmaxf(tm1, __shfl_xor_sync(0xffffffffu, tm1, 1));
            tm1 = fmaxf(tm1, __shfl_xor_sync(0xffffffffu, tm1, 2));
            float mn0 = fmaxf(m_[im][0], tm0), mn1 = fmaxf(m_[im][1], tm1);
            float al0 = exp2f(m_[im][0]-mn0), al1 = exp2f(m_[im][1]-mn1);
            m_[im][0] = mn0; m_[im][1] = mn1;
            float rs0 = 0.f, rs1 = 0.f;
            #pragma unroll
            for(int jn=0; jn<8; jn++){
                s[im][jn][0] = exp2f(s[im][jn][0]-mn0); rs0 += s[im][jn][0];
                s[im][jn][1] = exp2f(s[im][jn][1]-mn0); rs0 += s[im][jn][1];
                s[im][jn][2] = exp2f(s[im][jn][2]-mn1); rs1 += s[im][jn][2];
                s[im][jn][3] = exp2f(s[im][jn][3]-mn1); rs1 += s[im][jn][3];
            }
            rs0 += __shfl_xor_sync(0xffffffffu, rs0, 1);
            rs0 += __shfl_xor_sync(0xffffffffu, rs0, 2);
            rs1 += __shfl_xor_sync(0xffffffffu, rs1, 1);
            rs1 += __shfl_xor_sync(0xffffffffu, rs1, 2);
            l_[im][0] = l_[im][0]*al0 + rs0;
            l_[im][1] = l_[im][1]*al1 + rs1;
            #pragma unroll
            for(int jd=0; jd<8; jd++){
                o[im][jd][0]*=al0; o[im][jd][1]*=al0;
                o[im][jd][2]*=al1; o[im][jd][3]*=al1;
            }
        }

        // ---- O += P V : P fed straight from registers (C-frag == A-frag) ----
        #pragma unroll
        for(int kk=0; kk<4; kk++){
            uint32_t pf[2][4];
            #pragma unroll
            for(int im=0; im<2; im++){
                pf[im][0] = pack_h2(s[im][2*kk  ][0], s[im][2*kk  ][1]);
                pf[im][1] = pack_h2(s[im][2*kk  ][2], s[im][2*kk  ][3]);
                pf[im][2] = pack_h2(s[im][2*kk+1][0], s[im][2*kk+1][1]);
                pf[im][3] = pack_h2(s[im][2*kk+1][2], s[im][2*kk+1][3]);
            }
            #pragma unroll
            for(int p=0; p<4; p++){
                uint32_t vf[4];
                ldsm4(vf, sbase + 2*(vb + koff[p] + kk*16));
                mma_f16(o[0][2*p  ], pf[0], vf[0], vf[1]);
                mma_f16(o[1][2*p  ], pf[1], vf[0], vf[1]);
                mma_f16(o[0][2*p+1], pf[0], vf[2], vf[3]);
                mma_f16(o[1][2*p+1], pf[1], vf[2], vf[3]);
            }
        }
        __syncthreads();
    }

    // epilogue -> ctx fp16 [B,S,E]
    #pragma unroll
    for(int im=0; im<2; im++){
        float inv0 = 1.0f/l_[im][0], inv1 = 1.0f/l_[im][1];
        int gr0 = q0 + w*32 + im*16 + (lane>>2);
        #pragma unroll
        for(int jd=0; jd<8; jd++){
            int col = h*HDIM + jd*8 + (lane&3)*2;
            *(uint32_t*)&ctx[(size_t)(b*SEQ + gr0  )*EMB + col] =
                pack_h2(o[im][jd][0]*inv0, o[im][jd][1]*inv0);
            *(uint32_t*)&ctx[(size_t)(b*SEQ + gr0+8)*EMB + col] =
                pack_h2(o[im][jd][2]*inv1, o[im][jd][3]*inv1);
        }
    }
}

// =============================================================================
extern "C" void kernel_launch(void* const* d_in, const int* in_sizes, int n_in,
                              void* d_out, int out_size)
{
    const float* x    = (const float*)d_in[0];
    const int*   mask = (const int*)  d_in[1];
    const float* Wq   = (const float*)d_in[2];
    const float* bq   = (const float*)d_in[3];
    const float* Wk   = (const float*)d_in[4];
    const float* bk   = (const float*)d_in[5];
    const float* Wv   = (const float*)d_in[6];
    const float* bv   = (const float*)d_in[7];
    const float* Wo   = (const float*)d_in[8];
    const float* bo   = (const float*)d_in[9];
    float* out = (float*)d_out;

    __half *qp, *kp, *vp, *cp, *xp, *wp;
    float *bp;
    cudaGetSymbolAddress((void**)&qp, g_q);
    cudaGetSymbolAddress((void**)&kp, g_k);
    cudaGetSymbolAddress((void**)&vp, g_v);
    cudaGetSymbolAddress((void**)&cp, g_ctx);
    cudaGetSymbolAddress((void**)&xp, g_x);
    cudaGetSymbolAddress((void**)&wp, g_w);
    cudaGetSymbolAddress((void**)&bp, g_b);

    cudaFuncSetAttribute(gemm_nt,   cudaFuncAttributeMaxDynamicSharedMemorySize, GEMM_SMEM_BYTES);
    cudaFuncSetAttribute(flash_attn,cudaFuncAttributeMaxDynamicSharedMemorySize, FLASH_SMEM_BYTES);

    // 1) fused prep (f32 -> fp16)
    prep_k<<<(PREP_TOTAL+255)/256, 256>>>(
        (const float4*)x, (const float4*)Wq, (const float4*)Wk,
        (const float4*)Wv, (const float4*)Wo,
        bq, bk, bv,
        (uint2*)xp, (uint2*)wp, bp);

    // 2) fused QKV projection (N=3072)
    dim3 gqkv(3*EMB/GBN, MTOT/GBM);  // (24, 64)
    gemm_nt<<<gqkv, 256, GEMM_SMEM_BYTES>>>(xp, wp, bp, qp, kp, vp, nullptr, 1);

    // 3) flash attention
    dim3 fg(SEQ/FBQ, BATCH*HEADS);   // (16, 64)
    flash_attn<<<fg, 128, FLASH_SMEM_BYTES>>>(qp, kp, vp, mask, cp);

    // 4) output projection (f32 out)
    dim3 go(EMB/GBN, MTOT/GBM);      // (8, 64)
    gemm_nt<<<go, 256, GEMM_SMEM_BYTES>>>(cp, wp+3*(size_t)EMB*EMB, bo,
                                          nullptr, nullptr, nullptr, out, 0);
}

// round 14
// speedup vs baseline: 1.1240x; 1.0080x over previous
#include <cuda_runtime.h>
#include <cuda_fp16.h>
#include <cstdint>

#define BATCH 4
#define SEQ   2048
#define EMB   1024
#define HEADS 16
#define HDIM  64
#define MTOT  (BATCH*SEQ)   // 8192

// ---------------- scratch (device globals: allocation-free rule) -------------
__device__ __half g_q[MTOT*EMB];      // fp16, pre-scaled 1/8*log2e, [bh][s][d]
__device__ __half g_k[MTOT*EMB];      // fp16, [bh][s][d]
__device__ __half g_v[MTOT*EMB];      // fp16, TRANSPOSED [bh][d][s]
__device__ __half g_ctx[MTOT*EMB];    // fp16, [B,S,E]
__device__ __half g_x[MTOT*EMB];      // fp16 input
__device__ __half g_w[4*EMB*EMB];     // fp16 Wq,Wk,Wv,Wo (contiguous)
__device__ float  g_b[3*EMB];         // packed bq|bk|bv (f32)

// ---------------- PTX helpers ------------------------------------------------
__device__ __forceinline__ uint32_t pack_h2(float lo, float hi){
    __half2 h = __floats2half2_rn(lo, hi);
    return *(uint32_t*)&h;
}
__device__ __forceinline__ uint32_t h2exp2(uint32_t x){
    uint32_t y; asm("ex2.approx.f16x2 %0, %1;" : "=r"(y) : "r"(x)); return y;
}
__device__ __forceinline__ void ldsm4(uint32_t a[4], uint32_t saddr){
    asm volatile("ldmatrix.sync.aligned.m8n8.x4.shared.b16 {%0,%1,%2,%3}, [%4];"
        : "=r"(a[0]),"=r"(a[1]),"=r"(a[2]),"=r"(a[3]) : "r"(saddr));
}
__device__ __forceinline__ void ldsm2(uint32_t a[2], uint32_t saddr){
    asm volatile("ldmatrix.sync.aligned.m8n8.x2.shared.b16 {%0,%1}, [%2];"
        : "=r"(a[0]),"=r"(a[1]) : "r"(saddr));
}
__device__ __forceinline__ void mma_f16(float c[4], const uint32_t a[4],
                                        uint32_t b0, uint32_t b1){
    asm volatile(
        "mma.sync.aligned.m16n8k16.row.col.f32.f16.f16.f32 "
        "{%0,%1,%2,%3},{%4,%5,%6,%7},{%8,%9},{%0,%1,%2,%3};"
        : "+f"(c[0]),"+f"(c[1]),"+f"(c[2]),"+f"(c[3])
        : "r"(a[0]),"r"(a[1]),"r"(a[2]),"r"(a[3]),"r"(b0),"r"(b1));
}
__device__ __forceinline__ void cpa16(uint32_t dst, const void* src){
    asm volatile("cp.async.ca.shared.global [%0], [%1], 16;\n" :: "r"(dst), "l"(src));
}
__device__ __forceinline__ void cpa_commit(){ asm volatile("cp.async.commit_group;\n"); }
template<int N> __device__ __forceinline__ void cpa_wait(){
    asm volatile("cp.async.wait_group %0;\n" :: "n"(N));
}

// ---------------- fused prep: f32 -> fp16 x + 4 W, pack biases ---------------
#define N4X (MTOT*EMB/4)     // 2097152
#define N4W (EMB*EMB/4)      // 262144
__device__ __forceinline__ uint2 h4(float4 v){
    uint2 r; r.x = pack_h2(v.x, v.y); r.y = pack_h2(v.z, v.w); return r;
}
__global__ void prep_k(
    const float4* __restrict__ x,
    const float4* __restrict__ Wq, const float4* __restrict__ Wk,
    const float4* __restrict__ Wv, const float4* __restrict__ Wo,
    const float*  __restrict__ bq, const float* __restrict__ bk,
    const float*  __restrict__ bv,
    uint2* __restrict__ xp, uint2* __restrict__ wp, float* __restrict__ bp)
{
    int i = blockIdx.x*blockDim.x + threadIdx.x;
    if(i < N4X){
        xp[i] = h4(x[i]);
    } else if(i < N4X + 4*N4W){
        int j = i - N4X;
        int w = j >> 18;
        int off = j & (N4W-1);
        const float4* src = (w==0)?Wq : (w==1)?Wk : (w==2)?Wv : Wo;
        wp[(size_t)w*N4W + off] = h4(src[off]);
    } else {
        int j = i - (N4X + 4*N4W);
        if(j < 3*EMB){
            int seg = j >> 10, off = j & (EMB-1);
            const float* src = (seg==0)?bq : (seg==1)?bk : bv;
            bp[j] = src[off];
        }
    }
}
#define PREP_TOTAL (N4X + 4*N4W + 3*EMB)

// Q pre-scale: (1/8) * log2(e), so softmax can run in exp2 domain.
#define QSCALE (0.125f * 1.44269504f)

// =============================================================================
// fp16 NT GEMM (R11 config): 128x128 block, 8 warps (2x4), warp tile 64x32,
// m16n8k16, 3-stage cp.async, stride-40 fp16, 2 CTAs/SM.
// fused=1: N=3072 (Wq|Wk|Wv); Q scaled QSCALE; V stored transposed [bh][d][s].
// fused=0: flat f32 [M,1024] store.
// =============================================================================
#define GBM 128
#define GBN 128
#define GBK 32
#define ASTRH 40                          // fp16 units
#define A_STG_H (GBM*ASTRH)               // 5120
#define B_STG_H (GBN*ASTRH)               // 5120
#define STG_H   (A_STG_H + B_STG_H)       // 10240
#define GEMM_SMEM_BYTES (3*STG_H*2)       // 61440

__global__ __launch_bounds__(256, 2) void gemm_nt(
    const __half* __restrict__ A, const __half* __restrict__ W,
    const float* __restrict__ bias,
    __half* __restrict__ oQ, __half* __restrict__ oK, __half* __restrict__ oV,
    float* __restrict__ oF, int fused)
{
    extern __shared__ __half smh[];
    const int tid  = threadIdx.x;
    const int lane = tid & 31;
    const int wid  = tid >> 5;
    const int wm   = wid & 1, wn = wid >> 1;   // 2 (M) x 4 (N)
    const int m0 = blockIdx.y * GBM;
    const int n0 = blockIdx.x * GBN;
    const uint32_t sbase = (uint32_t)__cvta_generic_to_shared(smh);

    auto load_stage = [&](int kt, int st){
        const int k0 = kt*GBK;
        const int baseh = st*STG_H;
        const __half* ag = A + (size_t)m0*EMB + k0;
        #pragma unroll
        for(int i=0;i<2;i++){
            int idx = tid + i*256;
            int r = idx>>2, c16 = idx&3;
            cpa16(sbase + (uint32_t)(2*(baseh + r*ASTRH + c16*8)),
                  ag + (size_t)r*EMB + c16*8);
        }
        const __half* wg = W + (size_t)n0*EMB + k0;
        #pragma unroll
        for(int i=0;i<2;i++){
            int idx = tid + i*256;
            int r = idx>>2, c16 = idx&3;
            cpa16(sbase + (uint32_t)(2*(baseh + A_STG_H + r*ASTRH + c16*8)),
                  wg + (size_t)r*EMB + c16*8);
        }
        cpa_commit();
    };

    // ldmatrix lane offsets (fp16 units)
    const int q8 = lane >> 3, lr = lane & 7;
    uint32_t aoff[4], boff[2];
    #pragma unroll
    for(int im=0; im<4; im++)
        aoff[im] = (uint32_t)((wm*64 + im*16 + (lane&15))*ASTRH + (lane>>4)*8);
    #pragma unroll
    for(int p=0; p<2; p++)
        boff[p] = (uint32_t)(A_STG_H +
                   (wn*32 + p*16 + (q8>>1)*8 + lr)*ASTRH + (q8&1)*8);

    float acc[4][4][4] = {};

    load_stage(0, 0);
    load_stage(1, 1);
    const int NKT = EMB/GBK;   // 32
    for(int kt=0; kt<NKT; kt++){
        if(kt == NKT-1) cpa_wait<0>(); else cpa_wait<1>();
        __syncthreads();
        const uint32_t baseh = (uint32_t)((kt % 3)*STG_H);

        #pragma unroll
        for(int ks=0; ks<2; ks++){            // two k16 steps per K=32 chunk
            uint32_t a[4][4];
            #pragma unroll
            for(int im=0; im<4; im++)
                ldsm4(a[im], sbase + 2*(baseh + aoff[im] + ks*16));
            #pragma unroll
            for(int p=0; p<2; p++){
                uint32_t bf[4];
                ldsm4(bf, sbase + 2*(baseh + boff[p] + ks*16));
                #pragma unroll
                for(int im=0; im<4; im++){
                    mma_f16(acc[im][2*p  ], a[im], bf[0], bf[1]);
                    mma_f16(acc[im][2*p+1], a[im], bf[2], bf[3]);
                }
            }
        }
        if(kt+2 < NKT) load_stage(kt+2, (kt+2)%3);
    }

    // ---- epilogue ----
    int seg = 0;
    float scale = 1.0f;
    __half* outp = oQ;
    int n0s = n0;
    if(fused){
        seg  = n0 >> 10;
        n0s  = n0 & 1023;
        outp = (seg==0) ? oQ : (seg==1) ? oK : oV;
        scale = (seg==0) ? QSCALE : 1.0f;
    }
    #pragma unroll
    for(int im=0; im<4; im++){
        #pragma unroll
        for(int jn=0; jn<4; jn++){
            int nc = wn*32 + jn*8 + (lane&3)*2;
            float b0 = bias[n0+nc], b1 = bias[n0+nc+1];
            #pragma unroll
            for(int half_=0; half_<2; half_++){
                int r = m0 + wm*64 + im*16 + (lane>>2) + half_*8;
                float v0 = acc[im][jn][half_*2+0] + b0;
                float v1 = acc[im][jn][half_*2+1] + b1;
                if(fused){
                    int bidx = r >> 11;
                    int srow = r & (SEQ-1);
                    int ncol = n0s + nc;
                    int head = ncol >> 6, d = ncol & 63;
                    size_t bh = (size_t)(bidx*HEADS + head);
                    if(seg == 2){
                        outp[(bh*HDIM + d  )*SEQ + srow] = __float2half_rn(v0);
                        outp[(bh*HDIM + d+1)*SEQ + srow] = __float2half_rn(v1);
                    }else{
                        *(uint32_t*)&outp[(bh*SEQ + srow)*HDIM + d] =
                            pack_h2(v0*scale, v1*scale);
                    }
                }else{
                    *(float2*)&oF[(size_t)r*EMB + n0 + nc] = make_float2(v0, v1);
                }
            }
        }
    }
}

// =============================================================================
// Flash attention fp16 v4: 128 threads (4 warps), FBQ=128, M_warp=32.
// P from registers via ex2.approx.f16x2 (half the MUFU ops, zero extra packs).
// Row sums via ones-column in V (rows 64-71 of VT tile): l accumulated by the
// PV mma in fp32; no explicit sum/shfl-reduce/l bookkeeping.
// =============================================================================
#define FBQ 128
#define FBK 64
#define KSTRH 72
#define VROWS 72                          // 64 d-rows + 8 ones/zero rows
#define KS_H   0
#define KSTG_H (FBK*KSTRH)                // 4608
#define VS_H   (2*KSTG_H)                 // 9216
#define VSTG_H (VROWS*KSTRH)              // 5184
#define Q_H    (VS_H + 2*VSTG_H)          // 19584
#define Q_SZ_H (FBQ*KSTRH)                // 9216
#define BI_H   (Q_H + Q_SZ_H)             // 28800 halves
#define FLASH_SMEM_BYTES (BI_H*2 + 2*FBK*4 + 64)   // ~58.2 KB

__global__ __launch_bounds__(128, 2) void flash_attn(
    const __half* __restrict__ Qg_, const __half* __restrict__ Kg_,
    const __half* __restrict__ Vg_, const int* __restrict__ mask,
    __half* __restrict__ ctx)
{
    extern __shared__ __half smh[];
    float* smf = (float*)(smh + BI_H);
    const uint32_t sbase = (uint32_t)__cvta_generic_to_shared(smh);
    const int tid = threadIdx.x, lane = tid&31, w = tid>>5;
    const int bh = blockIdx.y, b = bh>>4, h = bh&15;
    const int q0 = blockIdx.x * FBQ;
    const __half* Qg = Qg_ + (size_t)bh*SEQ*HDIM;
    const __half* Kg = Kg_ + (size_t)bh*SEQ*HDIM;
    const __half* Vg = Vg_ + (size_t)bh*HDIM*SEQ;   // [d][s]

    #pragma unroll
    for(int i=0;i<8;i++){
        int idx = tid + i*128;
        int r = idx>>3, c16 = idx&7;
        cpa16(sbase + (uint32_t)(2*(Q_H + r*KSTRH + c16*8)),
              Qg + (size_t)(q0+r)*HDIM + c16*8);
    }
    cpa_commit();

    // ones/zero rows 64-71 of BOTH V stages (cp.async never writes them)
    for(int i = tid; i < 2*8*64; i += 128){
        int st = i >> 9;               // /512
        int rr = (i >> 6) & 7;         // 0..7
        int cc = i & 63;
        smh[VS_H + st*VSTG_H + (64+rr)*KSTRH + cc] =
            (rr == 0) ? __float2half(1.0f) : __float2half(0.0f);
    }

    auto loadKV = [&](int kt, int st){
        const int k0 = kt*FBK;
        #pragma unroll
        for(int i=0;i<4;i++){
            int idx = tid + i*128;
            int r = idx>>3, c16 = idx&7;
            cpa16(sbase + (uint32_t)(2*(KS_H + st*KSTG_H + r*KSTRH + c16*8)),
                  Kg + (size_t)(k0+r)*HDIM + c16*8);
        }
        #pragma unroll
        for(int i=0;i<4;i++){
            int idx = tid + i*128;
            int r = idx>>3, c16 = idx&7;   // r = d row
            cpa16(sbase + (uint32_t)(2*(VS_H + st*VSTG_H + r*KSTRH + c16*8)),
                  Vg + (size_t)r*SEQ + k0 + c16*8);
        }
        if(tid < FBK){
            int mv = mask[b*SEQ + k0 + tid];
            smf[st*FBK + tid] = mv ? 0.0f : -1e9f;
        }
        cpa_commit();
    };
    loadKV(0, 0);

    cpa_wait<1>();   // Q ready
    __syncthreads();

    const int q8 = lane >> 3, lr = lane & 7;
    uint32_t koff[4], qoff[2];
    #pragma unroll
    for(int p=0; p<4; p++)
        koff[p] = (uint32_t)((p*16 + (q8>>1)*8 + lr)*KSTRH + (q8&1)*8);
    const uint32_t voff1 = (uint32_t)((64 + lr)*KSTRH + q8*8);  // ones block (x2)
    #pragma unroll
    for(int im=0; im<2; im++)
        qoff[im] = (uint32_t)(Q_H + (w*32 + im*16 + (lane&15))*KSTRH + (lane>>4)*8);

    // Q fragments -> registers (4 k16-steps over d=64)
    uint32_t qf[4][2][4];
    #pragma unroll
    for(int kd=0; kd<4; kd++)
        #pragma unroll
        for(int im=0; im<2; im++)
            ldsm4(qf[kd][im], sbase + 2*(qoff[im] + kd*16));

    float m_[2][2] = {{-1e30f,-1e30f},{-1e30f,-1e30f}};
    float o[2][9][4] = {};   // [8] = ones-column block: row sums (l)

    const int NT = SEQ/FBK;   // 32
    for(int kt=0; kt<NT; kt++){
        if(kt+1 < NT){ loadKV(kt+1, (kt+1)&1); cpa_wait<1>(); }
        else         { cpa_wait<0>(); }
        __syncthreads();
        const int st = kt & 1;
        const uint32_t kb = (uint32_t)(KS_H + st*KSTG_H);
        const uint32_t vb = (uint32_t)(VS_H + st*VSTG_H);

        // ---- S = Q K^T (Q pre-scaled 1/8*log2e) ----
        float s[2][8][4] = {};
        #pragma unroll
        for(int kd=0; kd<4; kd++){
            #pragma unroll
            for(int p=0; p<4; p++){
                uint32_t kf[4];
                ldsm4(kf, sbase + 2*(kb + koff[p] + kd*16));
                mma_f16(s[0][2*p  ], qf[kd][0], kf[0], kf[1]);
                mma_f16(s[1][2*p  ], qf[kd][1], kf[0], kf[1]);
                mma_f16(s[0][2*p+1], qf[kd][0], kf[2], kf[3]);
                mma_f16(s[1][2*p+1], qf[kd][1], kf[2], kf[3]);
            }
        }

        // ---- bias + running max + rescale O (incl. l column) ----
        float mn0_[2], mn1_[2];
        #pragma unroll
        for(int im=0; im<2; im++){
            float tm0 = -1e30f, tm1 = -1e30f;
            #pragma unroll
            for(int jn=0; jn<8; jn++){
                int col = jn*8 + (lane&3)*2;
                float bb0 = smf[st*FBK + col];
                float bb1 = smf[st*FBK + col+1];
                s[im][jn][0] += bb0; tm0 = fmaxf(tm0, s[im][jn][0]);
                s[im][jn][1] += bb1; tm0 = fmaxf(tm0, s[im][jn][1]);
                s[im][jn][2] += bb0; tm1 = fmaxf(tm1, s[im][jn][2]);
                s[im][jn][3] += bb1; tm1 = fmaxf(tm1, s[im][jn][3]);
            }
            tm0 = fmaxf(tm0, __shfl_xor_sync(0xffffffffu, tm0, 1));
            tm0 = fmaxf(tm0, __shfl_xor_sync(0xffffffffu, tm0, 2));
            tm1 = fmaxf(tm1, __shfl_xor_sync(0xffffffffu, tm1, 1));
            tm1 = fmaxf(tm1, __shfl_xor_sync(0xffffffffu, tm1, 2));
            float mn0 = fmaxf(m_[im][0], tm0), mn1 = fmaxf(m_[im][1], tm1);
            float al0 = exp2f(m_[im][0]-mn0), al1 = exp2f(m_[im][1]-mn1);
            m_[im][0] = mn0; m_[im][1] = mn1;
            mn0_[im] = mn0; mn1_[im] = mn1;
            #pragma unroll
            for(int jd=0; jd<9; jd++){
                o[im][jd][0]*=al0; o[im][jd][1]*=al0;
                o[im][jd][2]*=al1; o[im][jd][3]*=al1;
            }
        }

        // ---- O += P V : P = ex2.f16x2 of (s - m), fed straight to mma ----
        #pragma unroll
        for(int kk=0; kk<4; kk++){
            uint32_t pf[2][4];
            #pragma unroll
            for(int im=0; im<2; im++){
                pf[im][0] = h2exp2(pack_h2(s[im][2*kk  ][0]-mn0_[im], s[im][2*kk  ][1]-mn0_[im]));
                pf[im][1] = h2exp2(pack_h2(s[im][2*kk  ][2]-mn1_[im], s[im][2*kk  ][3]-mn1_[im]));
                pf[im][2] = h2exp2(pack_h2(s[im][2*kk+1][0]-mn0_[im], s[im][2*kk+1][1]-mn0_[im]));
                pf[im][3] = h2exp2(pack_h2(s[im][2*kk+1][2]-mn1_[im], s[im][2*kk+1][3]-mn1_[im]));
            }
            #pragma unroll
            for(int p=0; p<4; p++){
                uint32_t vf[4];
                ldsm4(vf, sbase + 2*(vb + koff[p] + kk*16));
                mma_f16(o[0][2*p  ], pf[0], vf[0], vf[1]);
                mma_f16(o[1][2*p  ], pf[1], vf[0], vf[1]);
                mma_f16(o[0][2*p+1], pf[0], vf[2], vf[3]);
                mma_f16(o[1][2*p+1], pf[1], vf[2], vf[3]);
            }
            uint32_t vf1[2];
            ldsm2(vf1, sbase + 2*(vb + voff1 + kk*16));
            mma_f16(o[0][8], pf[0], vf1[0], vf1[1]);
            mma_f16(o[1][8], pf[1], vf1[0], vf1[1]);
        }
        __syncthreads();
    }

    // epilogue -> ctx fp16 [B,S,E]; l = ones-column of O (broadcast in quad)
    #pragma unroll
    for(int im=0; im<2; im++){
        float l0 = __shfl_sync(0xffffffffu, o[im][8][0], lane & ~3);
        float l1 = __shfl_sync(0xffffffffu, o[im][8][2], lane & ~3);
        float inv0 = 1.0f/l0, inv1 = 1.0f/l1;
        int gr0 = q0 + w*32 + im*16 + (lane>>2);
        #pragma unroll
        for(int jd=0; jd<8; jd++){
            int col = h*HDIM + jd*8 + (lane&3)*2;
            *(uint32_t*)&ctx[(size_t)(b*SEQ + gr0  )*EMB + col] =
                pack_h2(o[im][jd][0]*inv0, o[im][jd][1]*inv0);
            *(uint32_t*)&ctx[(size_t)(b*SEQ + gr0+8)*EMB + col] =
                pack_h2(o[im][jd][2]*inv1, o[im][jd][3]*inv1);
        }
    }
}

// =============================================================================
extern "C" void kernel_launch(void* const* d_in, const int* in_sizes, int n_in,
                              void* d_out, int out_size)
{
    const float* x    = (const float*)d_in[0];
    const int*   mask = (const int*)  d_in[1];
    const float* Wq   = (const float*)d_in[2];
    const float* bq   = (const float*)d_in[3];
    const float* Wk   = (const float*)d_in[4];
    const float* bk   = (const float*)d_in[5];
    const float* Wv   = (const float*)d_in[6];
    const float* bv   = (const float*)d_in[7];
    const float* Wo   = (const float*)d_in[8];
    const float* bo   = (const float*)d_in[9];
    float* out = (float*)d_out;

    __half *qp, *kp, *vp, *cp, *xp, *wp;
    float *bp;
    cudaGetSymbolAddress((void**)&qp, g_q);
    cudaGetSymbolAddress((void**)&kp, g_k);
    cudaGetSymbolAddress((void**)&vp, g_v);
    cudaGetSymbolAddress((void**)&cp, g_ctx);
    cudaGetSymbolAddress((void**)&xp, g_x);
    cudaGetSymbolAddress((void**)&wp, g_w);
    cudaGetSymbolAddress((void**)&bp, g_b);

    cudaFuncSetAttribute(gemm_nt,   cudaFuncAttributeMaxDynamicSharedMemorySize, GEMM_SMEM_BYTES);
    cudaFuncSetAttribute(flash_attn,cudaFuncAttributeMaxDynamicSharedMemorySize, FLASH_SMEM_BYTES);

    // 1) fused prep (f32 -> fp16)
    prep_k<<<(PREP_TOTAL+255)/256, 256>>>(
        (const float4*)x, (const float4*)Wq, (const float4*)Wk,
        (const float4*)Wv, (const float4*)Wo,
        bq, bk, bv,
        (uint2*)xp, (uint2*)wp, bp);

    // 2) fused QKV projection (N=3072)
    dim3 gqkv(3*EMB/GBN, MTOT/GBM);  // (24, 64)
    gemm_nt<<<gqkv, 256, GEMM_SMEM_BYTES>>>(xp, wp, bp, qp, kp, vp, nullptr, 1);

    // 3) flash attention
    dim3 fg(SEQ/FBQ, BATCH*HEADS);   // (16, 64)
    flash_attn<<<fg, 128, FLASH_SMEM_BYTES>>>(qp, kp, vp, mask, cp);

    // 4) output projection (f32 out)
    dim3 go(EMB/GBN, MTOT/GBM);      // (8, 64)
    gemm_nt<<<go, 256, GEMM_SMEM_BYTES>>>(cp, wp+3*(size_t)EMB*EMB, bo,
                                          nullptr, nullptr, nullptr, out, 0);
}

// round 15
// speedup vs baseline: 1.2145x; 1.0805x over previous
#include <cuda_runtime.h>
#include <cuda_fp16.h>
#include <cstdint>

#define BATCH 4
#define SEQ   2048
#define EMB   1024
#define HEADS 16
#define HDIM  64
#define MTOT  (BATCH*SEQ)   // 8192

// ---------------- scratch (device globals: allocation-free rule) -------------
__device__ __half g_q[MTOT*EMB];      // fp16, pre-scaled 1/8*log2e, [bh][s][d]
__device__ __half g_k[MTOT*EMB];      // fp16, [bh][s][d]
__device__ __half g_v[MTOT*EMB];      // fp16, TRANSPOSED [bh][d][s]
__device__ __half g_ctx[MTOT*EMB];    // fp16, [B,S,E]
__device__ __half g_x[MTOT*EMB];      // fp16 input
__device__ __half g_w[4*EMB*EMB];     // fp16 Wq,Wk,Wv,Wo (contiguous)
__device__ float  g_b[3*EMB];         // packed bq|bk|bv (f32)

// ---------------- PTX helpers ------------------------------------------------
__device__ __forceinline__ uint32_t pack_h2(float lo, float hi){
    __half2 h = __floats2half2_rn(lo, hi);
    return *(uint32_t*)&h;
}
__device__ __forceinline__ uint32_t h2exp2(uint32_t x){
    uint32_t y; asm("ex2.approx.f16x2 %0, %1;" : "=r"(y) : "r"(x)); return y;
}
__device__ __forceinline__ void ldsm4(uint32_t a[4], uint32_t saddr){
    asm volatile("ldmatrix.sync.aligned.m8n8.x4.shared.b16 {%0,%1,%2,%3}, [%4];"
        : "=r"(a[0]),"=r"(a[1]),"=r"(a[2]),"=r"(a[3]) : "r"(saddr));
}
__device__ __forceinline__ void ldsm2(uint32_t a[2], uint32_t saddr){
    asm volatile("ldmatrix.sync.aligned.m8n8.x2.shared.b16 {%0,%1}, [%2];"
        : "=r"(a[0]),"=r"(a[1]) : "r"(saddr));
}
__device__ __forceinline__ void mma_f16(float c[4], const uint32_t a[4],
                                        uint32_t b0, uint32_t b1){
    asm volatile(
        "mma.sync.aligned.m16n8k16.row.col.f32.f16.f16.f32 "
        "{%0,%1,%2,%3},{%4,%5,%6,%7},{%8,%9},{%0,%1,%2,%3};"
        : "+f"(c[0]),"+f"(c[1]),"+f"(c[2]),"+f"(c[3])
        : "r"(a[0]),"r"(a[1]),"r"(a[2]),"r"(a[3]),"r"(b0),"r"(b1));
}
__device__ __forceinline__ void cpa16(uint32_t dst, const void* src){
    asm volatile("cp.async.ca.shared.global [%0], [%1], 16;\n" :: "r"(dst), "l"(src));
}
__device__ __forceinline__ void cpa_commit(){ asm volatile("cp.async.commit_group;\n"); }
template<int N> __device__ __forceinline__ void cpa_wait(){
    asm volatile("cp.async.wait_group %0;\n" :: "n"(N));
}

// ---------------- fused prep: f32 -> fp16 x + 4 W, pack biases ---------------
#define N4X (MTOT*EMB/4)     // 2097152
#define N4W (EMB*EMB/4)      // 262144
__device__ __forceinline__ uint2 h4(float4 v){
    uint2 r; r.x = pack_h2(v.x, v.y); r.y = pack_h2(v.z, v.w); return r;
}
__global__ void prep_k(
    const float4* __restrict__ x,
    const float4* __restrict__ Wq, const float4* __restrict__ Wk,
    const float4* __restrict__ Wv, const float4* __restrict__ Wo,
    const float*  __restrict__ bq, const float* __restrict__ bk,
    const float*  __restrict__ bv,
    uint2* __restrict__ xp, uint2* __restrict__ wp, float* __restrict__ bp)
{
    int i = blockIdx.x*blockDim.x + threadIdx.x;
    if(i < N4X){
        xp[i] = h4(x[i]);
    } else if(i < N4X + 4*N4W){
        int j = i - N4X;
        int w = j >> 18;
        int off = j & (N4W-1);
        const float4* src = (w==0)?Wq : (w==1)?Wk : (w==2)?Wv : Wo;
        wp[(size_t)w*N4W + off] = h4(src[off]);
    } else {
        int j = i - (N4X + 4*N4W);
        if(j < 3*EMB){
            int seg = j >> 10, off = j & (EMB-1);
            const float* src = (seg==0)?bq : (seg==1)?bk : bv;
            bp[j] = src[off];
        }
    }
}
#define PREP_TOTAL (N4X + 4*N4W + 3*EMB)

// Q pre-scale: (1/8) * log2(e), so softmax can run in exp2 domain.
#define QSCALE (0.125f * 1.44269504f)

// =============================================================================
// fp16 NT GEMM v5: 128x128 block, 4 warps (2x2), warp tile 64x64, m16n8k16.
// ldsm:mma = 8:32 (4:1, same as flash). 3-stage cp.async, stride-40 fp16,
// 61 KB smem -> 2 CTAs/SM (8 warps/SM).
// fused=1: N=3072 (Wq|Wk|Wv); Q scaled QSCALE; V stored transposed [bh][d][s].
// fused=0: flat f32 [M,1024] store.
// =============================================================================
#define GBM 128
#define GBN 128
#define GBK 32
#define ASTRH 40                          // fp16 units
#define A_STG_H (GBM*ASTRH)               // 5120
#define B_STG_H (GBN*ASTRH)               // 5120
#define STG_H   (A_STG_H + B_STG_H)       // 10240
#define GEMM_SMEM_BYTES (3*STG_H*2)       // 61440

__global__ __launch_bounds__(128, 2) void gemm_nt(
    const __half* __restrict__ A, const __half* __restrict__ W,
    const float* __restrict__ bias,
    __half* __restrict__ oQ, __half* __restrict__ oK, __half* __restrict__ oV,
    float* __restrict__ oF, int fused)
{
    extern __shared__ __half smh[];
    const int tid  = threadIdx.x;
    const int lane = tid & 31;
    const int wid  = tid >> 5;
    const int wm   = wid & 1, wn = wid >> 1;   // 2 (M) x 2 (N) warps
    const int m0 = blockIdx.y * GBM;
    const int n0 = blockIdx.x * GBN;
    const uint32_t sbase = (uint32_t)__cvta_generic_to_shared(smh);

    auto load_stage = [&](int kt, int st){
        const int k0 = kt*GBK;
        const int baseh = st*STG_H;
        const __half* ag = A + (size_t)m0*EMB + k0;
        #pragma unroll
        for(int i=0;i<4;i++){
            int idx = tid + i*128;
            int r = idx>>2, c16 = idx&3;
            cpa16(sbase + (uint32_t)(2*(baseh + r*ASTRH + c16*8)),
                  ag + (size_t)r*EMB + c16*8);
        }
        const __half* wg = W + (size_t)n0*EMB + k0;
        #pragma unroll
        for(int i=0;i<4;i++){
            int idx = tid + i*128;
            int r = idx>>2, c16 = idx&3;
            cpa16(sbase + (uint32_t)(2*(baseh + A_STG_H + r*ASTRH + c16*8)),
                  wg + (size_t)r*EMB + c16*8);
        }
        cpa_commit();
    };

    // ldmatrix lane offsets (fp16 units)
    const int q8 = lane >> 3, lr = lane & 7;
    uint32_t aoff[4], boff[4];
    #pragma unroll
    for(int im=0; im<4; im++)
        aoff[im] = (uint32_t)((wm*64 + im*16 + (lane&15))*ASTRH + (lane>>4)*8);
    #pragma unroll
    for(int p=0; p<4; p++)
        boff[p] = (uint32_t)(A_STG_H +
                   (wn*64 + p*16 + (q8>>1)*8 + lr)*ASTRH + (q8&1)*8);

    float acc[4][8][4] = {};

    load_stage(0, 0);
    load_stage(1, 1);
    const int NKT = EMB/GBK;   // 32
    for(int kt=0; kt<NKT; kt++){
        if(kt == NKT-1) cpa_wait<0>(); else cpa_wait<1>();
        __syncthreads();
        const uint32_t baseh = (uint32_t)((kt % 3)*STG_H);

        #pragma unroll
        for(int ks=0; ks<2; ks++){            // two k16 steps per K=32 chunk
            uint32_t a[4][4];
            #pragma unroll
            for(int im=0; im<4; im++)
                ldsm4(a[im], sbase + 2*(baseh + aoff[im] + ks*16));
            #pragma unroll
            for(int p=0; p<4; p++){
                uint32_t bf[4];
                ldsm4(bf, sbase + 2*(baseh + boff[p] + ks*16));
                #pragma unroll
                for(int im=0; im<4; im++){
                    mma_f16(acc[im][2*p  ], a[im], bf[0], bf[1]);
                    mma_f16(acc[im][2*p+1], a[im], bf[2], bf[3]);
                }
            }
        }
        if(kt+2 < NKT) load_stage(kt+2, (kt+2)%3);
    }

    // ---- epilogue (direct from registers) ----
    int seg = 0;
    float scale = 1.0f;
    __half* outp = oQ;
    int n0s = n0;
    if(fused){
        seg  = n0 >> 10;
        n0s  = n0 & 1023;
        outp = (seg==0) ? oQ : (seg==1) ? oK : oV;
        scale = (seg==0) ? QSCALE : 1.0f;
    }
    #pragma unroll
    for(int im=0; im<4; im++){
        #pragma unroll
        for(int jn=0; jn<8; jn++){
            int nc = wn*64 + jn*8 + (lane&3)*2;
            float b0 = bias[n0+nc], b1 = bias[n0+nc+1];
            #pragma unroll
            for(int half_=0; half_<2; half_++){
                int r = m0 + wm*64 + im*16 + (lane>>2) + half_*8;
                float v0 = acc[im][jn][half_*2+0] + b0;
                float v1 = acc[im][jn][half_*2+1] + b1;
                if(fused){
                    int bidx = r >> 11;
                    int srow = r & (SEQ-1);
                    int ncol = n0s + nc;
                    int head = ncol >> 6, d = ncol & 63;
                    size_t bh = (size_t)(bidx*HEADS + head);
                    if(seg == 2){
                        outp[(bh*HDIM + d  )*SEQ + srow] = __float2half_rn(v0);
                        outp[(bh*HDIM + d+1)*SEQ + srow] = __float2half_rn(v1);
                    }else{
                        *(uint32_t*)&outp[(bh*SEQ + srow)*HDIM + d] =
                            pack_h2(v0*scale, v1*scale);
                    }
                }else{
                    *(float2*)&oF[(size_t)r*EMB + n0 + nc] = make_float2(v0, v1);
                }
            }
        }
    }
}

// =============================================================================
// Flash attention fp16 v4 (unchanged from R14): 128 threads, FBQ=128,
// M_warp=32, register-P via ex2.approx.f16x2, mma row-sums via ones column.
// =============================================================================
#define FBQ 128
#define FBK 64
#define KSTRH 72
#define VROWS 72                          // 64 d-rows + 8 ones/zero rows
#define KS_H   0
#define KSTG_H (FBK*KSTRH)                // 4608
#define VS_H   (2*KSTG_H)                 // 9216
#define VSTG_H (VROWS*KSTRH)              // 5184
#define Q_H    (VS_H + 2*VSTG_H)          // 19584
#define Q_SZ_H (FBQ*KSTRH)                // 9216
#define BI_H   (Q_H + Q_SZ_H)             // 28800 halves
#define FLASH_SMEM_BYTES (BI_H*2 + 2*FBK*4 + 64)

__global__ __launch_bounds__(128, 2) void flash_attn(
    const __half* __restrict__ Qg_, const __half* __restrict__ Kg_,
    const __half* __restrict__ Vg_, const int* __restrict__ mask,
    __half* __restrict__ ctx)
{
    extern __shared__ __half smh[];
    float* smf = (float*)(smh + BI_H);
    const uint32_t sbase = (uint32_t)__cvta_generic_to_shared(smh);
    const int tid = threadIdx.x, lane = tid&31, w = tid>>5;
    const int bh = blockIdx.y, b = bh>>4, h = bh&15;
    const int q0 = blockIdx.x * FBQ;
    const __half* Qg = Qg_ + (size_t)bh*SEQ*HDIM;
    const __half* Kg = Kg_ + (size_t)bh*SEQ*HDIM;
    const __half* Vg = Vg_ + (size_t)bh*HDIM*SEQ;   // [d][s]

    #pragma unroll
    for(int i=0;i<8;i++){
        int idx = tid + i*128;
        int r = idx>>3, c16 = idx&7;
        cpa16(sbase + (uint32_t)(2*(Q_H + r*KSTRH + c16*8)),
              Qg + (size_t)(q0+r)*HDIM + c16*8);
    }
    cpa_commit();

    // ones/zero rows 64-71 of BOTH V stages (cp.async never writes them)
    for(int i = tid; i < 2*8*64; i += 128){
        int st = i >> 9;
        int rr = (i >> 6) & 7;
        int cc = i & 63;
        smh[VS_H + st*VSTG_H + (64+rr)*KSTRH + cc] =
            (rr == 0) ? __float2half(1.0f) : __float2half(0.0f);
    }

    auto loadKV = [&](int kt, int st){
        const int k0 = kt*FBK;
        #pragma unroll
        for(int i=0;i<4;i++){
            int idx = tid + i*128;
            int r = idx>>3, c16 = idx&7;
            cpa16(sbase + (uint32_t)(2*(KS_H + st*KSTG_H + r*KSTRH + c16*8)),
                  Kg + (size_t)(k0+r)*HDIM + c16*8);
        }
        #pragma unroll
        for(int i=0;i<4;i++){
            int idx = tid + i*128;
            int r = idx>>3, c16 = idx&7;
            cpa16(sbase + (uint32_t)(2*(VS_H + st*VSTG_H + r*KSTRH + c16*8)),
                  Vg + (size_t)r*SEQ + k0 + c16*8);
        }
        if(tid < FBK){
            int mv = mask[b*SEQ + k0 + tid];
            smf[st*FBK + tid] = mv ? 0.0f : -1e9f;
        }
        cpa_commit();
    };
    loadKV(0, 0);

    cpa_wait<1>();
    __syncthreads();

    const int q8 = lane >> 3, lr = lane & 7;
    uint32_t koff[4], qoff[2];
    #pragma unroll
    for(int p=0; p<4; p++)
        koff[p] = (uint32_t)((p*16 + (q8>>1)*8 + lr)*KSTRH + (q8&1)*8);
    const uint32_t voff1 = (uint32_t)((64 + lr)*KSTRH + q8*8);
    #pragma unroll
    for(int im=0; im<2; im++)
        qoff[im] = (uint32_t)(Q_H + (w*32 + im*16 + (lane&15))*KSTRH + (lane>>4)*8);

    uint32_t qf[4][2][4];
    #pragma unroll
    for(int kd=0; kd<4; kd++)
        #pragma unroll
        for(int im=0; im<2; im++)
            ldsm4(qf[kd][im], sbase + 2*(qoff[im] + kd*16));

    float m_[2][2] = {{-1e30f,-1e30f},{-1e30f,-1e30f}};
    float o[2][9][4] = {};

    const int NT = SEQ/FBK;
    for(int kt=0; kt<NT; kt++){
        if(kt+1 < NT){ loadKV(kt+1, (kt+1)&1); cpa_wait<1>(); }
        else         { cpa_wait<0>(); }
        __syncthreads();
        const int st = kt & 1;
        const uint32_t kb = (uint32_t)(KS_H + st*KSTG_H);
        const uint32_t vb = (uint32_t)(VS_H + st*VSTG_H);

        float s[2][8][4] = {};
        #pragma unroll
        for(int kd=0; kd<4; kd++){
            #pragma unroll
            for(int p=0; p<4; p++){
                uint32_t kf[4];
                ldsm4(kf, sbase + 2*(kb + koff[p] + kd*16));
                mma_f16(s[0][2*p  ], qf[kd][0], kf[0], kf[1]);
                mma_f16(s[1][2*p  ], qf[kd][1], kf[0], kf[1]);
                mma_f16(s[0][2*p+1], qf[kd][0], kf[2], kf[3]);
                mma_f16(s[1][2*p+1], qf[kd][1], kf[2], kf[3]);
            }
        }

        float mn0_[2], mn1_[2];
        #pragma unroll
        for(int im=0; im<2; im++){
            float tm0 = -1e30f, tm1 = -1e30f;
            #pragma unroll
            for(int jn=0; jn<8; jn++){
                int col = jn*8 + (lane&3)*2;
                float bb0 = smf[st*FBK + col];
                float bb1 = smf[st*FBK + col+1];
                s[im][jn][0] += bb0; tm0 = fmaxf(tm0, s[im][jn][0]);
                s[im][jn][1] += bb1; tm0 = fmaxf(tm0, s[im][jn][1]);
                s[im][jn][2] += bb0; tm1 = fmaxf(tm1, s[im][jn][2]);
                s[im][jn][3] += bb1; tm1 = fmaxf(tm1, s[im][jn][3]);
            }
            tm0 = fmaxf(tm0, __shfl_xor_sync(0xffffffffu, tm0, 1));
            tm0 = fmaxf(tm0, __shfl_xor_sync(0xffffffffu, tm0, 2));
            tm1 = fmaxf(tm1, __shfl_xor_sync(0xffffffffu, tm1, 1));
            tm1 = fmaxf(tm1, __shfl_xor_sync(0xffffffffu, tm1, 2));
            float mn0 = fmaxf(m_[im][0], tm0), mn1 = fmaxf(m_[im][1], tm1);
            float al0 = exp2f(m_[im][0]-mn0), al1 = exp2f(m_[im][1]-mn1);
            m_[im][0] = mn0; m_[im][1] = mn1;
            mn0_[im] = mn0; mn1_[im] = mn1;
            #pragma unroll
            for(int jd=0; jd<9; jd++){
                o[im][jd][0]*=al0; o[im][jd][1]*=al0;
                o[im][jd][2]*=al1; o[im][jd][3]*=al1;
            }
        }

        #pragma unroll
        for(int kk=0; kk<4; kk++){
            uint32_t pf[2][4];
            #pragma unroll
            for(int im=0; im<2; im++){
                pf[im][0] = h2exp2(pack_h2(s[im][2*kk  ][0]-mn0_[im], s[im][2*kk  ][1]-mn0_[im]));
                pf[im][1] = h2exp2(pack_h2(s[im][2*kk  ][2]-mn1_[im], s[im][2*kk  ][3]-mn1_[im]));
                pf[im][2] = h2exp2(pack_h2(s[im][2*kk+1][0]-mn0_[im], s[im][2*kk+1][1]-mn0_[im]));
                pf[im][3] = h2exp2(pack_h2(s[im][2*kk+1][2]-mn1_[im], s[im][2*kk+1][3]-mn1_[im]));
            }
            #pragma unroll
            for(int p=0; p<4; p++){
                uint32_t vf[4];
                ldsm4(vf, sbase + 2*(vb + koff[p] + kk*16));
                mma_f16(o[0][2*p  ], pf[0], vf[0], vf[1]);
                mma_f16(o[1][2*p  ], pf[1], vf[0], vf[1]);
                mma_f16(o[0][2*p+1], pf[0], vf[2], vf[3]);
                mma_f16(o[1][2*p+1], pf[1], vf[2], vf[3]);
            }
            uint32_t vf1[2];
            ldsm2(vf1, sbase + 2*(vb + voff1 + kk*16));
            mma_f16(o[0][8], pf[0], vf1[0], vf1[1]);
            mma_f16(o[1][8], pf[1], vf1[0], vf1[1]);
        }
        __syncthreads();
    }

    #pragma unroll
    for(int im=0; im<2; im++){
        float l0 = __shfl_sync(0xffffffffu, o[im][8][0], lane & ~3);
        float l1 = __shfl_sync(0xffffffffu, o[im][8][2], lane & ~3);
        float inv0 = 1.0f/l0, inv1 = 1.0f/l1;
        int gr0 = q0 + w*32 + im*16 + (lane>>2);
        #pragma unroll
        for(int jd=0; jd<8; jd++){
            int col = h*HDIM + jd*8 + (lane&3)*2;
            *(uint32_t*)&ctx[(size_t)(b*SEQ + gr0  )*EMB + col] =
                pack_h2(o[im][jd][0]*inv0, o[im][jd][1]*inv0);
            *(uint32_t*)&ctx[(size_t)(b*SEQ + gr0+8)*EMB + col] =
                pack_h2(o[im][jd][2]*inv1, o[im][jd][3]*inv1);
        }
    }
}

// =============================================================================
extern "C" void kernel_launch(void* const* d_in, const int* in_sizes, int n_in,
                              void* d_out, int out_size)
{
    const float* x    = (const float*)d_in[0];
    const int*   mask = (const int*)  d_in[1];
    const float* Wq   = (const float*)d_in[2];
    const float* bq   = (const float*)d_in[3];
    const float* Wk   = (const float*)d_in[4];
    const float* bk   = (const float*)d_in[5];
    const float* Wv   = (const float*)d_in[6];
    const float* bv   = (const float*)d_in[7];
    const float* Wo   = (const float*)d_in[8];
    const float* bo   = (const float*)d_in[9];
    float* out = (float*)d_out;

    __half *qp, *kp, *vp, *cp, *xp, *wp;
    float *bp;
    cudaGetSymbolAddress((void**)&qp, g_q);
    cudaGetSymbolAddress((void**)&kp, g_k);
    cudaGetSymbolAddress((void**)&vp, g_v);
    cudaGetSymbolAddress((void**)&cp, g_ctx);
    cudaGetSymbolAddress((void**)&xp, g_x);
    cudaGetSymbolAddress((void**)&wp, g_w);
    cudaGetSymbolAddress((void**)&bp, g_b);

    cudaFuncSetAttribute(gemm_nt,   cudaFuncAttributeMaxDynamicSharedMemorySize, GEMM_SMEM_BYTES);
    cudaFuncSetAttribute(flash_attn,cudaFuncAttributeMaxDynamicSharedMemorySize, FLASH_SMEM_BYTES);

    // 1) fused prep (f32 -> fp16)
    prep_k<<<(PREP_TOTAL+255)/256, 256>>>(
        (const float4*)x, (const float4*)Wq, (const float4*)Wk,
        (const float4*)Wv, (const float4*)Wo,
        bq, bk, bv,
        (uint2*)xp, (uint2*)wp, bp);

    // 2) fused QKV projection (N=3072)
    dim3 gqkv(3*EMB/GBN, MTOT/GBM);  // (24, 64)
    gemm_nt<<<gqkv, 128, GEMM_SMEM_BYTES>>>(xp, wp, bp, qp, kp, vp, nullptr, 1);

    // 3) flash attention
    dim3 fg(SEQ/FBQ, BATCH*HEADS);   // (16, 64)
    flash_attn<<<fg, 128, FLASH_SMEM_BYTES>>>(qp, kp, vp, mask, cp);

    // 4) output projection (f32 out)
    dim3 go(EMB/GBN, MTOT/GBM);      // (8, 64)
    gemm_nt<<<go, 128, GEMM_SMEM_BYTES>>>(cp, wp+3*(size_t)EMB*EMB, bo,
                                          nullptr, nullptr, nullptr, out, 0);
}